// round 15
// baseline (speedup 1.0000x reference)
#include <cuda_runtime.h>
#include <cstdint>
#include <cstddef>

#define BB 32
#define SQ 2048
#define SK 2048
#define DD 64
#define QB 128           // q rows per CTA
#define KB 64            // k cols per tile (2 CTAs/SM)
#define NT 256
#define NTILES (SK/KB)   // 32
#define MWPR (SK/32)     // mask words per row = 64

#define KSTR 68          // K tile row stride (floats)
#define VSTR 72          // V tile row stride
#define PSTR 68          // P tile row stride (64 cols + pad)

#define KBUF (KB*KSTR)   // 4352 floats per K buffer
#define VBUF (KB*VSTR)   // 4608 floats per V buffer
#define MBUFW (QB*2)     // 256 mask words per buffer (2 words/row/tile)

// float-index offsets in dynamic smem
#define OFF_K 0                         // 2 x 4352 = 8704 (Q staging uses both)
#define OFF_V (2*KBUF)                  // 8704
#define OFF_P (OFF_V + 2*VBUF)          // 17920
#define OFF_M (OFF_P + QB*PSTR)         // 26624
#define SMEM_FLOATS (OFF_M + 2*MBUFW)   // 27136
#define SMEM_BYTES  (SMEM_FLOATS*4)     // 108544 B -> 2 CTAs/SM

__device__ uint32_t g_maskbits[BB * SQ * MWPR];  // packed mask bits (16.8 MB)
__device__ uint32_t g_ktf[BB * SK * DD];         // K pre-rounded to tf32 (16.8 MB)
__device__ uint32_t g_vtf[BB * SK * DD];         // V pre-rounded to tf32 (16.8 MB)

static __device__ __forceinline__ uint32_t f2tf(float x) {
    uint32_t r; asm("cvt.rna.tf32.f32 %0, %1;" : "=r"(r) : "f"(x)); return r;
}
static __device__ __forceinline__ void mma8(float& d0, float& d1, float& d2, float& d3,
                                            uint32_t a0, uint32_t a1, uint32_t a2, uint32_t a3,
                                            uint32_t b0, uint32_t b1) {
    asm volatile("mma.sync.aligned.m16n8k8.row.col.f32.tf32.tf32.f32 "
                 "{%0,%1,%2,%3}, {%4,%5,%6,%7}, {%8,%9}, {%0,%1,%2,%3};"
                 : "+f"(d0), "+f"(d1), "+f"(d2), "+f"(d3)
                 : "r"(a0), "r"(a1), "r"(a2), "r"(a3), "r"(b0), "r"(b1));
}
static __device__ __forceinline__ void cpasync16(uint32_t dst, const void* src) {
    asm volatile("cp.async.cg.shared.global [%0], [%1], 16;" :: "r"(dst), "l"(src));
}
static __device__ __forceinline__ void cpasync8(uint32_t dst, const void* src) {
    asm volatile("cp.async.ca.shared.global [%0], [%1], 8;" :: "r"(dst), "l"(src));
}

// ---- prepass A: round K and V to tf32 once (67 MB streaming, ~14 us) ----
__global__ void __launch_bounds__(256)
kv_round(const float* __restrict__ Kg, const float* __restrict__ Vg)
{
    const int N4 = BB * SK * DD / 4;
    for (int i = blockIdx.x * 256 + threadIdx.x; i < N4; i += gridDim.x * 256) {
        float4 k = ((const float4*)Kg)[i];
        uint4 kt;
        kt.x = f2tf(k.x); kt.y = f2tf(k.y); kt.z = f2tf(k.z); kt.w = f2tf(k.w);
        ((uint4*)g_ktf)[i] = kt;
        float4 v = ((const float4*)Vg)[i];
        uint4 vt;
        vt.x = f2tf(v.x); vt.y = f2tf(v.y); vt.z = f2tf(v.z); vt.w = f2tf(v.w);
        ((uint4*)g_vtf)[i] = vt;
    }
}

// ---- prepass B: pack int32 mask -> bitmask, MLP=8 int4 loads + 8-lane reduce_or ----
// bit i of word w = (mask[w*32+i] != 0)
#define MP_UNROLL 8
__global__ void __launch_bounds__(256)
mask_pack(const int* __restrict__ Mg)
{
    const int lane  = threadIdx.x & 31;
    const int warp  = blockIdx.x * 8 + (threadIdx.x >> 5);
    const int nwarps = gridDim.x * 8;
    const uint32_t grp = 0xFFu << (8 * (lane >> 3));
    const int shift = 4 * (lane & 7);
    const size_t total = (size_t)BB * SQ * MWPR;

    for (size_t wbase = (size_t)warp * (MP_UNROLL * 4); wbase < total;
         wbase += (size_t)nwarps * (MP_UNROLL * 4)) {
        int4 v[MP_UNROLL];
        #pragma unroll
        for (int u = 0; u < MP_UNROLL; u++)
            v[u] = ((const int4*)Mg)[wbase * 8 + u * 32 + lane];
        #pragma unroll
        for (int u = 0; u < MP_UNROLL; u++) {
            uint32_t nib = (uint32_t)(v[u].x != 0)
                         | ((uint32_t)(v[u].y != 0) << 1)
                         | ((uint32_t)(v[u].z != 0) << 2)
                         | ((uint32_t)(v[u].w != 0) << 3);
            uint32_t word = __reduce_or_sync(grp, nib << shift);
            if ((lane & 7) == 0)
                g_maskbits[wbase + u * 4 + (lane >> 3)] = word;
        }
    }
}

__global__ void __launch_bounds__(NT, 2)
attn_pass1(const float* __restrict__ Qg,
           float* __restrict__ attn, float* __restrict__ Og)
{
    extern __shared__ float sm[];
    const uint32_t smb = (uint32_t)__cvta_generic_to_shared(sm);
    uint32_t* Pu = (uint32_t*)(sm + OFF_P);

    const int tid  = threadIdx.x;
    const int w    = tid >> 5;
    const int lane = tid & 31;
    const int q    = lane & 3;        // col pair within fragment
    const int g    = lane >> 2;       // row within fragment
    const int b    = blockIdx.y;
    const int qbase = blockIdx.x * QB;

    const int r0 = w * 16 + g;        // local q row (and r0+8)
    const size_t grow0 = (size_t)b * SQ + qbase + r0;
    const size_t grow1 = grow0 + 8;

    // ---- stage Q (scaled 0.125, single tf32) via the two K buffers, lift frags ----
    {
        uint32_t* QH = (uint32_t*)(sm + OFF_K);   // 128 rows x KSTR spans both K buffers
        const float4* Qv = (const float4*)(Qg + ((size_t)b * SQ + qbase) * DD);
        #pragma unroll
        for (int it = 0; it < (QB * DD / 4) / NT; it++) {
            int v = tid + it * NT;
            int row = v >> 4, c = (v & 15) * 4;
            float4 x = Qv[v];
            uint4 hi;
            hi.x = f2tf(x.x * 0.125f);
            hi.y = f2tf(x.y * 0.125f);
            hi.z = f2tf(x.z * 0.125f);
            hi.w = f2tf(x.w * 0.125f);
            *(uint4*)&QH[row * KSTR + c] = hi;
        }
    }
    __syncthreads();

    uint32_t qhi[8][4];
    {
        uint32_t* QH = (uint32_t*)(sm + OFF_K);
        #pragma unroll
        for (int s = 0; s < 8; s++) {
            const int c0 = s * 8 + q;
            qhi[s][0] = QH[r0 * KSTR + c0];
            qhi[s][1] = QH[(r0 + 8) * KSTR + c0];
            qhi[s][2] = QH[r0 * KSTR + c0 + 4];
            qhi[s][3] = QH[(r0 + 8) * KSTR + c0 + 4];
        }
    }
    __syncthreads();   // Q staging done; K buffers free for the pipeline

    const uint32_t* Kbase = g_ktf + (size_t)b * SK * DD;
    const uint32_t* Vbase = g_vtf + (size_t)b * SK * DD;
    const uint32_t* Mbase = g_maskbits + ((size_t)b * SQ + qbase) * MWPR;

    // ---- cp.async tile loader: pre-rounded tf32 K/V + packed mask bits ----
    auto issue_tile = [&](int t, int buf) {
        const uint4* Kv = (const uint4*)(Kbase + (size_t)t * KB * DD);
        const uint4* Vv = (const uint4*)(Vbase + (size_t)t * KB * DD);
        const uint32_t kd = smb + (OFF_K + buf * KBUF) * 4;
        const uint32_t vd = smb + (OFF_V + buf * VBUF) * 4;
        #pragma unroll
        for (int it = 0; it < (KB * DD / 4) / NT; it++) {
            int v = tid + it * NT;
            int row = v >> 4, c = (v & 15) * 4;
            cpasync16(kd + (row * KSTR + c) * 4, Kv + v);
            cpasync16(vd + (row * VSTR + c) * 4, Vv + v);
        }
        if (tid < QB) {
            const uint32_t md = smb + (OFF_M + buf * MBUFW) * 4;
            cpasync8(md + tid * 8, Mbase + (size_t)tid * MWPR + t * 2);
        }
        asm volatile("cp.async.commit_group;" ::: "memory");
    };

    issue_tile(0, 0);

    float oacc[8][4];
    #pragma unroll
    for (int i = 0; i < 8; i++)
        oacc[i][0] = oacc[i][1] = oacc[i][2] = oacc[i][3] = 0.f;
    float lsum0 = 0.f, lsum1 = 0.f;

    for (int t = 0; t < NTILES; t++) {
        if (t + 1 < NTILES) {
            issue_tile(t + 1, (t + 1) & 1);
            asm volatile("cp.async.wait_group 1;" ::: "memory");
        } else {
            asm volatile("cp.async.wait_group 0;" ::: "memory");
        }
        __syncthreads();   // tile t visible (already tf32 — no convert phase)

        const uint32_t* KHu = (const uint32_t*)(sm + OFF_K + (t & 1) * KBUF);
        const uint32_t* VTu = (const uint32_t*)(sm + OFF_V + (t & 1) * VBUF);
        const uint32_t* Mw  = (const uint32_t*)(sm + OFF_M + (t & 1) * MBUFW);

        // per-thread mask words for its two rows (broadcast LDS)
        uint32_t mw0[2], mw1[2];
        #pragma unroll
        for (int j = 0; j < 2; j++) {
            mw0[j] = Mw[r0 * 2 + j];
            mw1[j] = Mw[(r0 + 8) * 2 + j];
        }

        // ---- QK (single tf32, even/odd-s accumulator pair) + fused epilogue ----
        #pragma unroll 1
        for (int nb = 0; nb < KB / 8; nb++) {
            float a0 = 0.f, a1 = 0.f, a2 = 0.f, a3 = 0.f;     // even s
            float c0 = 0.f, c1 = 0.f, c2 = 0.f, c3 = 0.f;     // odd s
            const int nrow = nb * 8 + g;
            #pragma unroll
            for (int s = 0; s < 8; s += 2) {
                const int cc0 = s * 8 + q;
                const int cc1 = (s + 1) * 8 + q;
                const uint32_t e0 = KHu[nrow * KSTR + cc0];
                const uint32_t e1 = KHu[nrow * KSTR + cc0 + 4];
                const uint32_t o0 = KHu[nrow * KSTR + cc1];
                const uint32_t o1 = KHu[nrow * KSTR + cc1 + 4];
                mma8(a0, a1, a2, a3, qhi[s][0], qhi[s][1], qhi[s][2], qhi[s][3], e0, e1);
                mma8(c0, c1, c2, c3, qhi[s+1][0], qhi[s+1][1], qhi[s+1][2], qhi[s+1][3], o0, o1);
            }
            const float s00 = a0 + c0, s01 = a1 + c1, s10 = a2 + c2, s11 = a3 + c3;

            const uint32_t b0 = mw0[nb >> 2] >> ((nb & 3) * 8 + 2 * q);
            const uint32_t b1 = mw1[nb >> 2] >> ((nb & 3) * 8 + 2 * q);
            float e00 = (b0 & 1u) ? __expf(s00) : 0.f;
            float e01 = (b0 & 2u) ? __expf(s01) : 0.f;
            float e10 = (b1 & 1u) ? __expf(s10) : 0.f;
            float e11 = (b1 & 2u) ? __expf(s11) : 0.f;

            const int col = t * KB + nb * 8 + 2 * q;
            float2 w0; w0.x = e00; w0.y = e01;
            float2 w1; w1.x = e10; w1.y = e11;
            *(float2*)(attn + grow0 * SK + col) = w0;
            *(float2*)(attn + grow1 * SK + col) = w1;
            lsum0 += e00 + e01;
            lsum1 += e10 + e11;

            uint2 p0; p0.x = f2tf(e00); p0.y = f2tf(e01);
            uint2 p1; p1.x = f2tf(e10); p1.y = f2tf(e11);
            *(uint2*)&Pu[r0 * PSTR + nb * 8 + 2 * q] = p0;        // warp-private strip
            *(uint2*)&Pu[(r0 + 8) * PSTR + nb * 8 + 2 * q] = p1;
        }

        // ---- O += P @ V (k=64: 8 steps; n=64: 8 independent chains) ----
        #pragma unroll 1
        for (int s2 = 0; s2 < KB / 8; s2++) {
            const int cc = s2 * 8 + q;
            const uint32_t pa0 = Pu[r0 * PSTR + cc];
            const uint32_t pa1 = Pu[(r0 + 8) * PSTR + cc];
            const uint32_t pa2 = Pu[r0 * PSTR + cc + 4];
            const uint32_t pa3 = Pu[(r0 + 8) * PSTR + cc + 4];
            const int vr0 = s2 * 8 + q;
            #pragma unroll
            for (int nb2 = 0; nb2 < 8; nb2++) {
                const uint32_t vb0 = VTu[vr0 * VSTR + nb2 * 8 + g];
                const uint32_t vb1 = VTu[(vr0 + 4) * VSTR + nb2 * 8 + g];
                mma8(oacc[nb2][0], oacc[nb2][1], oacc[nb2][2], oacc[nb2][3],
                     pa0, pa1, pa2, pa3, vb0, vb1);
            }
        }
        __syncthreads();   // all warps done with buf[t&1] before it is refilled
    }

    // ---- finalize: row sums via butterfly within 4-lane groups ----
    #pragma unroll
    for (int off = 1; off <= 2; off <<= 1) {
        lsum0 += __shfl_xor_sync(0xffffffffu, lsum0, off);
        lsum1 += __shfl_xor_sync(0xffffffffu, lsum1, off);
    }
    const float inv0 = 1.0f / lsum0;
    const float inv1 = 1.0f / lsum1;

    // ---- write O (scaled) ----
    #pragma unroll
    for (int nb2 = 0; nb2 < 8; nb2++) {
        float2 o0; o0.x = oacc[nb2][0] * inv0; o0.y = oacc[nb2][1] * inv0;
        float2 o1; o1.x = oacc[nb2][2] * inv1; o1.y = oacc[nb2][3] * inv1;
        *(float2*)(Og + grow0 * DD + nb2 * 8 + 2 * q) = o0;
        *(float2*)(Og + grow1 * DD + nb2 * 8 + 2 * q) = o1;
    }

    // ---- fused normalize: scale this CTA's own 128 x 2048 attn slab ----
    float* invs = sm + OFF_P;          // reuse P strip for 128 row-invs
    if (q == 0) {
        invs[r0] = inv0;
        invs[r0 + 8] = inv1;
    }
    __syncthreads();                   // invs visible + attn writes visible (CUDA block fence)

    float4* Arow = (float4*)(attn + ((size_t)b * SQ + qbase) * SK);
    #pragma unroll 4
    for (int i = tid; i < QB * SK / 4; i += NT) {
        const int row = i >> 9;        // SK/4 = 512 float4 per row
        const float inv = invs[row];
        float4 x = Arow[i];
        x.x *= inv; x.y *= inv; x.z *= inv; x.w *= inv;
        Arow[i] = x;
    }
}

extern "C" void kernel_launch(void* const* d_in, const int* in_sizes, int n_in,
                              void* d_out, int out_size)
{
    const float* Q    = (const float*)d_in[0];
    const float* K    = (const float*)d_in[1];
    const float* V    = (const float*)d_in[2];
    const int*   mask = (const int*)d_in[3];

    float* attn = (float*)d_out;                   // [B, SQ, SK]
    float* outp = attn + (size_t)BB * SQ * SK;     // [B, SQ, D]

    cudaFuncSetAttribute(attn_pass1,
                         cudaFuncAttributeMaxDynamicSharedMemorySize, SMEM_BYTES);

    kv_round<<<1024, 256>>>(K, V);
    mask_pack<<<2048, 256>>>(mask);
    dim3 grid(SQ / QB, BB);
    attn_pass1<<<grid, NT, SMEM_BYTES>>>(Q, attn, outp);
}

// round 16
// speedup vs baseline: 1.0402x; 1.0402x over previous
#include <cuda_runtime.h>
#include <cstdint>
#include <cstddef>

#define BB 32
#define SQ 2048
#define SK 2048
#define DD 64
#define QB 128           // q rows per CTA
#define KB 64            // k cols per tile (2 CTAs/SM)
#define NT 256
#define NTILES (SK/KB)   // 32
#define MWPR (SK/32)     // mask words per row = 64

#define KSTR 68          // K tile row stride (floats)
#define VSTR 72          // V tile row stride
#define PSTR 68          // P tile row stride (64 cols + pad)

#define KBUF (KB*KSTR)   // 4352 floats per K buffer
#define VBUF (KB*VSTR)   // 4608 floats per V buffer
#define MBUFW (QB*2)     // 256 mask words per buffer (2 words/row/tile)

// float-index offsets in dynamic smem
#define OFF_K 0                         // 2 x 4352 = 8704 (Q staging uses both)
#define OFF_V (2*KBUF)                  // 8704
#define OFF_P (OFF_V + 2*VBUF)          // 17920
#define OFF_M (OFF_P + QB*PSTR)         // 26624
#define SMEM_FLOATS (OFF_M + 2*MBUFW)   // 27136
#define SMEM_BYTES  (SMEM_FLOATS*4)     // 108544 B -> 2 CTAs/SM

__device__ float    g_inv[BB * SQ];              // per-row 1/rowsum scratch
__device__ uint32_t g_maskbits[BB * SQ * MWPR];  // packed mask bits (16.8 MB)
__device__ uint32_t g_ktf[BB * SK * DD];         // K pre-rounded to tf32 (16.8 MB)
__device__ uint32_t g_vtf[BB * SK * DD];         // V pre-rounded to tf32 (16.8 MB)

static __device__ __forceinline__ uint32_t f2tf(float x) {
    uint32_t r; asm("cvt.rna.tf32.f32 %0, %1;" : "=r"(r) : "f"(x)); return r;
}
static __device__ __forceinline__ void mma8(float& d0, float& d1, float& d2, float& d3,
                                            uint32_t a0, uint32_t a1, uint32_t a2, uint32_t a3,
                                            uint32_t b0, uint32_t b1) {
    asm volatile("mma.sync.aligned.m16n8k8.row.col.f32.tf32.tf32.f32 "
                 "{%0,%1,%2,%3}, {%4,%5,%6,%7}, {%8,%9}, {%0,%1,%2,%3};"
                 : "+f"(d0), "+f"(d1), "+f"(d2), "+f"(d3)
                 : "r"(a0), "r"(a1), "r"(a2), "r"(a3), "r"(b0), "r"(b1));
}
static __device__ __forceinline__ void cpasync16(uint32_t dst, const void* src) {
    asm volatile("cp.async.cg.shared.global [%0], [%1], 16;" :: "r"(dst), "l"(src));
}
static __device__ __forceinline__ void cpasync8(uint32_t dst, const void* src) {
    asm volatile("cp.async.ca.shared.global [%0], [%1], 8;" :: "r"(dst), "l"(src));
}

// ---- fused prepass: blocks [0,256) round K/V to tf32; blocks [256,2048) pack mask ----
// Both are pure streaming on disjoint data; running them in one launch lets the
// combined 621 MB hit the streaming DRAM ceiling instead of serializing.
#define MP_UNROLL 8
#define PRE_KV_BLOCKS 256
#define PRE_BLOCKS 2048
__global__ void __launch_bounds__(256)
prepass(const float* __restrict__ Kg, const float* __restrict__ Vg,
        const int* __restrict__ Mg)
{
    if (blockIdx.x < PRE_KV_BLOCKS) {
        // ---- K/V tf32 rounding (67 MB) ----
        const int N4 = BB * SK * DD / 4;
        for (int i = blockIdx.x * 256 + threadIdx.x; i < N4; i += PRE_KV_BLOCKS * 256) {
            float4 k = ((const float4*)Kg)[i];
            uint4 kt;
            kt.x = f2tf(k.x); kt.y = f2tf(k.y); kt.z = f2tf(k.z); kt.w = f2tf(k.w);
            ((uint4*)g_ktf)[i] = kt;
            float4 v = ((const float4*)Vg)[i];
            uint4 vt;
            vt.x = f2tf(v.x); vt.y = f2tf(v.y); vt.z = f2tf(v.z); vt.w = f2tf(v.w);
            ((uint4*)g_vtf)[i] = vt;
        }
    } else {
        // ---- mask packing (537 MB read, 16.8 MB write) ----
        // bit i of word w = (mask[w*32+i] != 0)
        const int lane  = threadIdx.x & 31;
        const int warp  = (blockIdx.x - PRE_KV_BLOCKS) * 8 + (threadIdx.x >> 5);
        const int nwarps = (PRE_BLOCKS - PRE_KV_BLOCKS) * 8;
        const uint32_t grp = 0xFFu << (8 * (lane >> 3));
        const int shift = 4 * (lane & 7);
        const size_t total = (size_t)BB * SQ * MWPR;

        for (size_t wbase = (size_t)warp * (MP_UNROLL * 4); wbase < total;
             wbase += (size_t)nwarps * (MP_UNROLL * 4)) {
            int4 v[MP_UNROLL];
            #pragma unroll
            for (int u = 0; u < MP_UNROLL; u++)
                v[u] = ((const int4*)Mg)[wbase * 8 + u * 32 + lane];
            #pragma unroll
            for (int u = 0; u < MP_UNROLL; u++) {
                uint32_t nib = (uint32_t)(v[u].x != 0)
                             | ((uint32_t)(v[u].y != 0) << 1)
                             | ((uint32_t)(v[u].z != 0) << 2)
                             | ((uint32_t)(v[u].w != 0) << 3);
                uint32_t word = __reduce_or_sync(grp, nib << shift);
                if ((lane & 7) == 0)
                    g_maskbits[wbase + u * 4 + (lane >> 3)] = word;
            }
        }
    }
}

__global__ void __launch_bounds__(NT, 2)
attn_pass1(const float* __restrict__ Qg,
           float* __restrict__ attn, float* __restrict__ Og)
{
    extern __shared__ float sm[];
    const uint32_t smb = (uint32_t)__cvta_generic_to_shared(sm);
    uint32_t* Pu = (uint32_t*)(sm + OFF_P);

    const int tid  = threadIdx.x;
    const int w    = tid >> 5;
    const int lane = tid & 31;
    const int q    = lane & 3;        // col pair within fragment
    const int g    = lane >> 2;       // row within fragment
    const int b    = blockIdx.y;
    const int qbase = blockIdx.x * QB;

    const int r0 = w * 16 + g;        // local q row (and r0+8)
    const size_t grow0 = (size_t)b * SQ + qbase + r0;
    const size_t grow1 = grow0 + 8;

    // ---- stage Q (scaled 0.125, single tf32) via the two K buffers, lift frags ----
    {
        uint32_t* QH = (uint32_t*)(sm + OFF_K);   // 128 rows x KSTR spans both K buffers
        const float4* Qv = (const float4*)(Qg + ((size_t)b * SQ + qbase) * DD);
        #pragma unroll
        for (int it = 0; it < (QB * DD / 4) / NT; it++) {
            int v = tid + it * NT;
            int row = v >> 4, c = (v & 15) * 4;
            float4 x = Qv[v];
            uint4 hi;
            hi.x = f2tf(x.x * 0.125f);
            hi.y = f2tf(x.y * 0.125f);
            hi.z = f2tf(x.z * 0.125f);
            hi.w = f2tf(x.w * 0.125f);
            *(uint4*)&QH[row * KSTR + c] = hi;
        }
    }
    __syncthreads();

    uint32_t qhi[8][4];
    {
        uint32_t* QH = (uint32_t*)(sm + OFF_K);
        #pragma unroll
        for (int s = 0; s < 8; s++) {
            const int c0 = s * 8 + q;
            qhi[s][0] = QH[r0 * KSTR + c0];
            qhi[s][1] = QH[(r0 + 8) * KSTR + c0];
            qhi[s][2] = QH[r0 * KSTR + c0 + 4];
            qhi[s][3] = QH[(r0 + 8) * KSTR + c0 + 4];
        }
    }
    __syncthreads();   // Q staging done; K buffers free for the pipeline

    const uint32_t* Kbase = g_ktf + (size_t)b * SK * DD;
    const uint32_t* Vbase = g_vtf + (size_t)b * SK * DD;
    const uint32_t* Mbase = g_maskbits + ((size_t)b * SQ + qbase) * MWPR;

    // ---- cp.async tile loader: pre-rounded tf32 K/V + packed mask bits ----
    auto issue_tile = [&](int t, int buf) {
        const uint4* Kv = (const uint4*)(Kbase + (size_t)t * KB * DD);
        const uint4* Vv = (const uint4*)(Vbase + (size_t)t * KB * DD);
        const uint32_t kd = smb + (OFF_K + buf * KBUF) * 4;
        const uint32_t vd = smb + (OFF_V + buf * VBUF) * 4;
        #pragma unroll
        for (int it = 0; it < (KB * DD / 4) / NT; it++) {
            int v = tid + it * NT;
            int row = v >> 4, c = (v & 15) * 4;
            cpasync16(kd + (row * KSTR + c) * 4, Kv + v);
            cpasync16(vd + (row * VSTR + c) * 4, Vv + v);
        }
        if (tid < QB) {
            const uint32_t md = smb + (OFF_M + buf * MBUFW) * 4;
            cpasync8(md + tid * 8, Mbase + (size_t)tid * MWPR + t * 2);
        }
        asm volatile("cp.async.commit_group;" ::: "memory");
    };

    issue_tile(0, 0);

    float oacc[8][4];
    #pragma unroll
    for (int i = 0; i < 8; i++)
        oacc[i][0] = oacc[i][1] = oacc[i][2] = oacc[i][3] = 0.f;
    float lsum0 = 0.f, lsum1 = 0.f;

    for (int t = 0; t < NTILES; t++) {
        if (t + 1 < NTILES) {
            issue_tile(t + 1, (t + 1) & 1);
            asm volatile("cp.async.wait_group 1;" ::: "memory");
        } else {
            asm volatile("cp.async.wait_group 0;" ::: "memory");
        }
        __syncthreads();   // tile t visible (already tf32 — no convert phase)

        const uint32_t* KHu = (const uint32_t*)(sm + OFF_K + (t & 1) * KBUF);
        const uint32_t* VTu = (const uint32_t*)(sm + OFF_V + (t & 1) * VBUF);
        const uint32_t* Mw  = (const uint32_t*)(sm + OFF_M + (t & 1) * MBUFW);

        // per-thread mask words for its two rows (broadcast LDS)
        uint32_t mw0[2], mw1[2];
        #pragma unroll
        for (int j = 0; j < 2; j++) {
            mw0[j] = Mw[r0 * 2 + j];
            mw1[j] = Mw[(r0 + 8) * 2 + j];
        }

        // ---- QK (single tf32, even/odd-s accumulator pair) + fused epilogue ----
        #pragma unroll 1
        for (int nb = 0; nb < KB / 8; nb++) {
            float a0 = 0.f, a1 = 0.f, a2 = 0.f, a3 = 0.f;     // even s
            float c0 = 0.f, c1 = 0.f, c2 = 0.f, c3 = 0.f;     // odd s
            const int nrow = nb * 8 + g;
            #pragma unroll
            for (int s = 0; s < 8; s += 2) {
                const int cc0 = s * 8 + q;
                const int cc1 = (s + 1) * 8 + q;
                const uint32_t e0 = KHu[nrow * KSTR + cc0];
                const uint32_t e1 = KHu[nrow * KSTR + cc0 + 4];
                const uint32_t o0 = KHu[nrow * KSTR + cc1];
                const uint32_t o1 = KHu[nrow * KSTR + cc1 + 4];
                mma8(a0, a1, a2, a3, qhi[s][0], qhi[s][1], qhi[s][2], qhi[s][3], e0, e1);
                mma8(c0, c1, c2, c3, qhi[s+1][0], qhi[s+1][1], qhi[s+1][2], qhi[s+1][3], o0, o1);
            }
            const float s00 = a0 + c0, s01 = a1 + c1, s10 = a2 + c2, s11 = a3 + c3;

            const uint32_t b0 = mw0[nb >> 2] >> ((nb & 3) * 8 + 2 * q);
            const uint32_t b1 = mw1[nb >> 2] >> ((nb & 3) * 8 + 2 * q);
            float e00 = (b0 & 1u) ? __expf(s00) : 0.f;
            float e01 = (b0 & 2u) ? __expf(s01) : 0.f;
            float e10 = (b1 & 1u) ? __expf(s10) : 0.f;
            float e11 = (b1 & 2u) ? __expf(s11) : 0.f;

            const int col = t * KB + nb * 8 + 2 * q;
            float2 w0; w0.x = e00; w0.y = e01;
            float2 w1; w1.x = e10; w1.y = e11;
            *(float2*)(attn + grow0 * SK + col) = w0;
            *(float2*)(attn + grow1 * SK + col) = w1;
            lsum0 += e00 + e01;
            lsum1 += e10 + e11;

            uint2 p0; p0.x = f2tf(e00); p0.y = f2tf(e01);
            uint2 p1; p1.x = f2tf(e10); p1.y = f2tf(e11);
            *(uint2*)&Pu[r0 * PSTR + nb * 8 + 2 * q] = p0;        // warp-private strip
            *(uint2*)&Pu[(r0 + 8) * PSTR + nb * 8 + 2 * q] = p1;
        }

        // ---- O += P @ V (k=64: 8 steps; n=64: 8 independent chains) ----
        #pragma unroll 1
        for (int s2 = 0; s2 < KB / 8; s2++) {
            const int cc = s2 * 8 + q;
            const uint32_t pa0 = Pu[r0 * PSTR + cc];
            const uint32_t pa1 = Pu[(r0 + 8) * PSTR + cc];
            const uint32_t pa2 = Pu[r0 * PSTR + cc + 4];
            const uint32_t pa3 = Pu[(r0 + 8) * PSTR + cc + 4];
            const int vr0 = s2 * 8 + q;
            #pragma unroll
            for (int nb2 = 0; nb2 < 8; nb2++) {
                const uint32_t vb0 = VTu[vr0 * VSTR + nb2 * 8 + g];
                const uint32_t vb1 = VTu[(vr0 + 4) * VSTR + nb2 * 8 + g];
                mma8(oacc[nb2][0], oacc[nb2][1], oacc[nb2][2], oacc[nb2][3],
                     pa0, pa1, pa2, pa3, vb0, vb1);
            }
        }
        __syncthreads();   // all warps done with buf[t&1] before it is refilled
    }

    // ---- finalize: row sums via butterfly within 4-lane groups ----
    #pragma unroll
    for (int off = 1; off <= 2; off <<= 1) {
        lsum0 += __shfl_xor_sync(0xffffffffu, lsum0, off);
        lsum1 += __shfl_xor_sync(0xffffffffu, lsum1, off);
    }
    const float inv0 = 1.0f / lsum0;
    const float inv1 = 1.0f / lsum1;
    if (q == 0) {
        g_inv[grow0] = inv0;
        g_inv[grow1] = inv1;
    }

    #pragma unroll
    for (int nb2 = 0; nb2 < 8; nb2++) {
        float2 o0; o0.x = oacc[nb2][0] * inv0; o0.y = oacc[nb2][1] * inv0;
        float2 o1; o1.x = oacc[nb2][2] * inv1; o1.y = oacc[nb2][3] * inv1;
        *(float2*)(Og + grow0 * DD + nb2 * 8 + 2 * q) = o0;
        *(float2*)(Og + grow1 * DD + nb2 * 8 + 2 * q) = o1;
    }
}

// ---- pass 2: normalize attn rows by 1/rowsum ----
__global__ void __launch_bounds__(256)
attn_norm(float* __restrict__ attn)
{
    const int row = blockIdx.x;
    const float inv = g_inv[row];
    float4* p = (float4*)(attn + (size_t)row * SK);
    const int i = threadIdx.x;
    #pragma unroll
    for (int k = 0; k < 2; k++) {
        float4 x = p[i + k * 256];
        x.x *= inv; x.y *= inv; x.z *= inv; x.w *= inv;
        p[i + k * 256] = x;
    }
}

extern "C" void kernel_launch(void* const* d_in, const int* in_sizes, int n_in,
                              void* d_out, int out_size)
{
    const float* Q    = (const float*)d_in[0];
    const float* K    = (const float*)d_in[1];
    const float* V    = (const float*)d_in[2];
    const int*   mask = (const int*)d_in[3];

    float* attn = (float*)d_out;                   // [B, SQ, SK]
    float* outp = attn + (size_t)BB * SQ * SK;     // [B, SQ, D]

    cudaFuncSetAttribute(attn_pass1,
                         cudaFuncAttributeMaxDynamicSharedMemorySize, SMEM_BYTES);

    prepass<<<PRE_BLOCKS, 256>>>(K, V, mask);
    dim3 grid(SQ / QB, BB);
    attn_pass1<<<grid, NT, SMEM_BYTES>>>(Q, attn, outp);
    attn_norm<<<BB * SQ, 256>>>(attn);
}

// round 17
// speedup vs baseline: 1.3141x; 1.2633x over previous
#include <cuda_runtime.h>
#include <cuda_fp16.h>
#include <cstdint>
#include <cstddef>

#define BB 32
#define SQ 2048
#define SK 2048
#define DD 64
#define QB 128           // q rows per CTA
#define KB 64            // k cols per tile
#define NT 256
#define NTILES (SK/KB)   // 32
#define MWPR (SK/32)     // mask words per row = 64

#define KSTRW 36         // K tile row stride in uint32 words (32 data + 4 pad) -> (4g+q)%32 conflict-free
#define VSTRW 36         // V^T tile row stride (words)
#define PSTRW 36         // P strip row stride (words)

#define KBUF_W (KB*KSTRW)   // 2304 words per K buffer
#define VBUF_W (DD*VSTRW)   // 2304 words per V buffer
#define MBUFW  (QB*2)       // 256 mask words per buffer

// word-index offsets in dynamic smem
#define OFF_K 0                          // 2 x 2304 (Q staging spans both)
#define OFF_V (2*KBUF_W)                 // 4608
#define OFF_P (OFF_V + 2*VBUF_W)         // 9216
#define OFF_M (OFF_P + QB*PSTRW)         // 13824
#define SMEM_WORDS (OFF_M + 2*MBUFW)     // 14336
#define SMEM_BYTES (SMEM_WORDS*4)        // 57344 B -> 2+ CTAs/SM

__device__ float    g_inv[BB * SQ];               // per-row 1/rowsum
__device__ uint32_t g_maskbits[BB * SQ * MWPR];   // packed mask bits (16.8 MB)
__device__ uint32_t g_kh[BB * SK * DD / 2];       // K as f16 [b][key][d]      (8.4 MB)
__device__ uint32_t g_vt[BB * DD * SK / 2];       // V^T as f16 [b][d][key]    (8.4 MB)

static __device__ __forceinline__ uint32_t pkh2(float lo, float hi) {
    __half2 h = __floats2half2_rn(lo, hi);
    return *(uint32_t*)&h;
}
static __device__ __forceinline__ void mma16(float& d0, float& d1, float& d2, float& d3,
                                             uint32_t a0, uint32_t a1, uint32_t a2, uint32_t a3,
                                             uint32_t b0, uint32_t b1) {
    asm volatile("mma.sync.aligned.m16n8k16.row.col.f32.f16.f16.f32 "
                 "{%0,%1,%2,%3}, {%4,%5,%6,%7}, {%8,%9}, {%0,%1,%2,%3};"
                 : "+f"(d0), "+f"(d1), "+f"(d2), "+f"(d3)
                 : "r"(a0), "r"(a1), "r"(a2), "r"(a3), "r"(b0), "r"(b1));
}
static __device__ __forceinline__ void cpasync16(uint32_t dst, const void* src) {
    asm volatile("cp.async.cg.shared.global [%0], [%1], 16;" :: "r"(dst), "l"(src));
}
static __device__ __forceinline__ void cpasync8(uint32_t dst, const void* src) {
    asm volatile("cp.async.ca.shared.global [%0], [%1], 8;" :: "r"(dst), "l"(src));
}

// ---- fused prepass ----
// blocks [0,256):        K f32 -> f16 row-major
// blocks [256,1280):     V f32 -> f16 transposed per (batch, key-tile) 64x64 block
// blocks [1280,3072):    mask int32 -> bitmask
#define MP_UNROLL 8
#define PRE_K_BLOCKS 256
#define PRE_V_BLOCKS 1024
#define PRE_BLOCKS 3072
__global__ void __launch_bounds__(256)
prepass(const float* __restrict__ Kg, const float* __restrict__ Vg,
        const int* __restrict__ Mg)
{
    __shared__ uint16_t st[64 * 72];   // V transpose staging (only used by V blocks)

    if (blockIdx.x < PRE_K_BLOCKS) {
        const int N4 = BB * SK * DD / 4;
        for (int i = blockIdx.x * 256 + threadIdx.x; i < N4; i += PRE_K_BLOCKS * 256) {
            float4 k = ((const float4*)Kg)[i];
            uint2 o;
            o.x = pkh2(k.x, k.y);
            o.y = pkh2(k.z, k.w);
            ((uint2*)g_kh)[i] = o;
        }
    } else if (blockIdx.x < PRE_K_BLOCKS + PRE_V_BLOCKS) {
        const int vb = blockIdx.x - PRE_K_BLOCKS;
        const int bb = vb >> 5;         // batch
        const int kt = vb & 31;         // key tile (64 keys)
        const int tid = threadIdx.x;
        // read 64x64 f32 tile coalesced, stage transposed as f16
        const float4* Vt4 = (const float4*)(Vg + ((size_t)bb * SK + (size_t)kt * 64) * DD);
        #pragma unroll
        for (int it = 0; it < 4; it++) {
            int j = tid + it * 256;            // 1024 float4
            int key = j >> 4, dc = j & 15;     // d chunk of 4
            float4 x = Vt4[j];
            st[(dc * 4 + 0) * 72 + key] = __half_as_ushort(__float2half_rn(x.x));
            st[(dc * 4 + 1) * 72 + key] = __half_as_ushort(__float2half_rn(x.y));
            st[(dc * 4 + 2) * 72 + key] = __half_as_ushort(__float2half_rn(x.z));
            st[(dc * 4 + 3) * 72 + key] = __half_as_ushort(__float2half_rn(x.w));
        }
        __syncthreads();
        // write out rows of V^T: [d][key], 32 words per d-row
        #pragma unroll
        for (int it = 0; it < 8; it++) {
            int o = tid + it * 256;            // 2048 words
            int d = o >> 5, wi = o & 31;
            uint32_t wlo = st[d * 72 + 2 * wi];
            uint32_t whi = st[d * 72 + 2 * wi + 1];
            g_vt[((size_t)bb * DD + d) * (SK / 2) + kt * 32 + wi] = wlo | (whi << 16);
        }
    } else {
        // mask packing: bit i of word w = (mask[w*32+i] != 0)
        const int lane  = threadIdx.x & 31;
        const int warp  = (blockIdx.x - PRE_K_BLOCKS - PRE_V_BLOCKS) * 8 + (threadIdx.x >> 5);
        const int nwarps = (PRE_BLOCKS - PRE_K_BLOCKS - PRE_V_BLOCKS) * 8;
        const uint32_t grp = 0xFFu << (8 * (lane >> 3));
        const int shift = 4 * (lane & 7);
        const size_t total = (size_t)BB * SQ * MWPR;

        for (size_t wbase = (size_t)warp * (MP_UNROLL * 4); wbase < total;
             wbase += (size_t)nwarps * (MP_UNROLL * 4)) {
            int4 v[MP_UNROLL];
            #pragma unroll
            for (int u = 0; u < MP_UNROLL; u++)
                v[u] = ((const int4*)Mg)[wbase * 8 + u * 32 + lane];
            #pragma unroll
            for (int u = 0; u < MP_UNROLL; u++) {
                uint32_t nib = (uint32_t)(v[u].x != 0)
                             | ((uint32_t)(v[u].y != 0) << 1)
                             | ((uint32_t)(v[u].z != 0) << 2)
                             | ((uint32_t)(v[u].w != 0) << 3);
                uint32_t word = __reduce_or_sync(grp, nib << shift);
                if ((lane & 7) == 0)
                    g_maskbits[wbase + u * 4 + (lane >> 3)] = word;
            }
        }
    }
}

__global__ void __launch_bounds__(NT, 2)
attn_pass1(const float* __restrict__ Qg,
           float* __restrict__ attn, float* __restrict__ Og)
{
    extern __shared__ uint32_t smw[];
    const uint32_t smb = (uint32_t)__cvta_generic_to_shared(smw);
    uint32_t* Pu = smw + OFF_P;

    const int tid  = threadIdx.x;
    const int w    = tid >> 5;
    const int lane = tid & 31;
    const int q    = lane & 3;
    const int g    = lane >> 2;
    const int b    = blockIdx.y;
    const int qbase = blockIdx.x * QB;

    const int r0 = w * 16 + g;
    const size_t grow0 = (size_t)b * SQ + qbase + r0;
    const size_t grow1 = grow0 + 8;

    // ---- stage Q (scaled 0.125, f16) into K region, lift A-fragments ----
    {
        uint32_t* QW = smw + OFF_K;       // 128 rows x KSTRW words
        const float4* Qv = (const float4*)(Qg + ((size_t)b * SQ + qbase) * DD);
        #pragma unroll
        for (int it = 0; it < (QB * DD / 4) / NT; it++) {
            int v = tid + it * NT;
            int row = v >> 4, c4 = v & 15;
            float4 x = Qv[v];
            QW[row * KSTRW + c4 * 2]     = pkh2(x.x * 0.125f, x.y * 0.125f);
            QW[row * KSTRW + c4 * 2 + 1] = pkh2(x.z * 0.125f, x.w * 0.125f);
        }
    }
    __syncthreads();

    uint32_t qh[4][4];
    {
        uint32_t* QW = smw + OFF_K;
        #pragma unroll
        for (int s = 0; s < 4; s++) {
            const int base = s * 8;
            qh[s][0] = QW[r0 * KSTRW + base + q];
            qh[s][1] = QW[(r0 + 8) * KSTRW + base + q];
            qh[s][2] = QW[r0 * KSTRW + base + q + 4];
            qh[s][3] = QW[(r0 + 8) * KSTRW + base + q + 4];
        }
    }
    __syncthreads();   // Q staging done

    const uint32_t* Kbase = g_kh + (size_t)b * SK * (DD / 2);
    const uint32_t* Vbase = g_vt + (size_t)b * DD * (SK / 2);
    const uint32_t* Mbase = g_maskbits + ((size_t)b * SQ + qbase) * MWPR;

    // ---- cp.async tile loader: f16 K rows, f16 V^T rows, mask bits ----
    auto issue_tile = [&](int t, int buf) {
        const uint32_t kd = smb + (OFF_K + buf * KBUF_W) * 4;
        const uint32_t vd = smb + (OFF_V + buf * VBUF_W) * 4;
        // K: 64 rows x 8 chunks of 16B
        #pragma unroll
        for (int it = 0; it < (64 * 8) / NT; it++) {
            int v = tid + it * NT;
            int row = v >> 3, c = v & 7;
            cpasync16(kd + (row * KSTRW + c * 4) * 4,
                      Kbase + ((size_t)(t * 64 + row)) * 32 + c * 4);
            cpasync16(vd + (row * VSTRW + c * 4) * 4,
                      Vbase + (size_t)row * (SK / 2) + t * 32 + c * 4);
        }
        if (tid < QB) {
            const uint32_t md = smb + (OFF_M + buf * MBUFW) * 4;
            cpasync8(md + tid * 8, Mbase + (size_t)tid * MWPR + t * 2);
        }
        asm volatile("cp.async.commit_group;" ::: "memory");
    };

    issue_tile(0, 0);

    float oacc[8][4];
    #pragma unroll
    for (int i = 0; i < 8; i++)
        oacc[i][0] = oacc[i][1] = oacc[i][2] = oacc[i][3] = 0.f;
    float lsum0 = 0.f, lsum1 = 0.f;

    for (int t = 0; t < NTILES; t++) {
        if (t + 1 < NTILES) {
            issue_tile(t + 1, (t + 1) & 1);
            asm volatile("cp.async.wait_group 1;" ::: "memory");
        } else {
            asm volatile("cp.async.wait_group 0;" ::: "memory");
        }
        __syncthreads();

        const uint32_t* KW = smw + OFF_K + (t & 1) * KBUF_W;
        const uint32_t* VW = smw + OFF_V + (t & 1) * VBUF_W;
        const uint32_t* Mw = smw + OFF_M + (t & 1) * MBUFW;

        uint32_t mw0[2], mw1[2];
        #pragma unroll
        for (int j = 0; j < 2; j++) {
            mw0[j] = Mw[r0 * 2 + j];
            mw1[j] = Mw[(r0 + 8) * 2 + j];
        }

        // ---- QK (f16 m16n8k16, 4 k-steps, even/odd chains) + fused epilogue ----
        #pragma unroll 1
        for (int nb = 0; nb < KB / 8; nb++) {
            float a0 = 0.f, a1 = 0.f, a2 = 0.f, a3 = 0.f;
            float c0 = 0.f, c1 = 0.f, c2 = 0.f, c3 = 0.f;
            const int nrow = nb * 8 + g;
            #pragma unroll
            for (int s = 0; s < 4; s += 2) {
                const uint32_t e0 = KW[nrow * KSTRW + s * 8 + q];
                const uint32_t e1 = KW[nrow * KSTRW + s * 8 + q + 4];
                const uint32_t o0 = KW[nrow * KSTRW + (s + 1) * 8 + q];
                const uint32_t o1 = KW[nrow * KSTRW + (s + 1) * 8 + q + 4];
                mma16(a0, a1, a2, a3, qh[s][0], qh[s][1], qh[s][2], qh[s][3], e0, e1);
                mma16(c0, c1, c2, c3, qh[s+1][0], qh[s+1][1], qh[s+1][2], qh[s+1][3], o0, o1);
            }
            const float s00 = a0 + c0, s01 = a1 + c1, s10 = a2 + c2, s11 = a3 + c3;

            const uint32_t b0 = mw0[nb >> 2] >> ((nb & 3) * 8 + 2 * q);
            const uint32_t b1 = mw1[nb >> 2] >> ((nb & 3) * 8 + 2 * q);
            float e00 = (b0 & 1u) ? __expf(s00) : 0.f;
            float e01 = (b0 & 2u) ? __expf(s01) : 0.f;
            float e10 = (b1 & 1u) ? __expf(s10) : 0.f;
            float e11 = (b1 & 2u) ? __expf(s11) : 0.f;

            const int col = t * KB + nb * 8 + 2 * q;
            float2 w0; w0.x = e00; w0.y = e01;
            float2 w1; w1.x = e10; w1.y = e11;
            *(float2*)(attn + grow0 * SK + col) = w0;
            *(float2*)(attn + grow1 * SK + col) = w1;
            lsum0 += e00 + e01;
            lsum1 += e10 + e11;

            Pu[r0 * PSTRW + nb * 4 + q]       = pkh2(e00, e01);   // warp-private strip
            Pu[(r0 + 8) * PSTRW + nb * 4 + q] = pkh2(e10, e11);
        }

        // ---- O += P @ V^T (f16 m16n8k16: 4 k-steps x 8 d-blocks) ----
        #pragma unroll 1
        for (int s2 = 0; s2 < 4; s2++) {
            const int base = s2 * 8;
            const uint32_t pa0 = Pu[r0 * PSTRW + base + q];
            const uint32_t pa1 = Pu[(r0 + 8) * PSTRW + base + q];
            const uint32_t pa2 = Pu[r0 * PSTRW + base + q + 4];
            const uint32_t pa3 = Pu[(r0 + 8) * PSTRW + base + q + 4];
            #pragma unroll
            for (int nb2 = 0; nb2 < 8; nb2++) {
                const uint32_t vb0 = VW[(nb2 * 8 + g) * VSTRW + base + q];
                const uint32_t vb1 = VW[(nb2 * 8 + g) * VSTRW + base + q + 4];
                mma16(oacc[nb2][0], oacc[nb2][1], oacc[nb2][2], oacc[nb2][3],
                      pa0, pa1, pa2, pa3, vb0, vb1);
            }
        }
        __syncthreads();
    }

    // ---- finalize: row sums via butterfly within 4-lane groups ----
    #pragma unroll
    for (int off = 1; off <= 2; off <<= 1) {
        lsum0 += __shfl_xor_sync(0xffffffffu, lsum0, off);
        lsum1 += __shfl_xor_sync(0xffffffffu, lsum1, off);
    }
    const float inv0 = 1.0f / lsum0;
    const float inv1 = 1.0f / lsum1;
    if (q == 0) {
        g_inv[grow0] = inv0;
        g_inv[grow1] = inv1;
    }

    #pragma unroll
    for (int nb2 = 0; nb2 < 8; nb2++) {
        float2 o0; o0.x = oacc[nb2][0] * inv0; o0.y = oacc[nb2][1] * inv0;
        float2 o1; o1.x = oacc[nb2][2] * inv1; o1.y = oacc[nb2][3] * inv1;
        *(float2*)(Og + grow0 * DD + nb2 * 8 + 2 * q) = o0;
        *(float2*)(Og + grow1 * DD + nb2 * 8 + 2 * q) = o1;
    }
}

// ---- pass 2: normalize attn rows by 1/rowsum ----
__global__ void __launch_bounds__(256)
attn_norm(float* __restrict__ attn)
{
    const int row = blockIdx.x;
    const float inv = g_inv[row];
    float4* p = (float4*)(attn + (size_t)row * SK);
    const int i = threadIdx.x;
    #pragma unroll
    for (int k = 0; k < 2; k++) {
        float4 x = p[i + k * 256];
        x.x *= inv; x.y *= inv; x.z *= inv; x.w *= inv;
        p[i + k * 256] = x;
    }
}

extern "C" void kernel_launch(void* const* d_in, const int* in_sizes, int n_in,
                              void* d_out, int out_size)
{
    const float* Q    = (const float*)d_in[0];
    const float* K    = (const float*)d_in[1];
    const float* V    = (const float*)d_in[2];
    const int*   mask = (const int*)d_in[3];

    float* attn = (float*)d_out;                   // [B, SQ, SK]
    float* outp = attn + (size_t)BB * SQ * SK;     // [B, SQ, D]

    cudaFuncSetAttribute(attn_pass1,
                         cudaFuncAttributeMaxDynamicSharedMemorySize, SMEM_BYTES);

    prepass<<<PRE_BLOCKS, 256>>>(K, V, mask);
    dim3 grid(SQ / QB, BB);
    attn_pass1<<<grid, NT, SMEM_BYTES>>>(Q, attn, outp);
    attn_norm<<<BB * SQ, 256>>>(attn);
}